// round 1
// baseline (speedup 1.0000x reference)
#include <cuda_runtime.h>

// ---------------------------------------------------------------------------
// Problem constants
// ---------------------------------------------------------------------------
constexpr int Bn  = 8;
constexpr int CH  = 128;
constexpr int H   = 80;
constexpr int W   = 80;
constexpr int HW  = H * W;
constexpr int MID = 16;
constexpr float EPS = 1e-5f;

// ---------------------------------------------------------------------------
// Scratch (static __device__ globals — allocation-free per harness rules)
// ---------------------------------------------------------------------------
__device__ float g_h[Bn * CH * HW];            // silu(conv_off1)        26 MB
__device__ float g_off[Bn * 27 * HW];          // raw offset/mask conv    5.5 MB
__device__ float g_vals[Bn * CH * 9 * HW];     // deform samples        236 MB
__device__ float g_iral[Bn * CH * HW];         // ir_aligned             26 MB
__device__ float g_g1[Bn * MID * HW];          // gate stage-1           3.3 MB
__device__ float g_gate[Bn * HW];              // final gate             0.2 MB

#define DEV __device__ __forceinline__

DEV float sigm_(float x) { return 1.0f / (1.0f + __expf(-x)); }
DEV float silu_(float x) { return x * sigm_(x); }

// ---------------------------------------------------------------------------
// Input fetch per conv mode
//   MODE 0: concat(rgb, ir)            Cin=256, 3x3 -> g_h      (silu(v+b))
//   MODE 1: concat(g*iral, (1-g)*rgb)  Cin=256, 3x3 -> out      (silu(bn)+res)
//   MODE 2: g_vals (c*9+k layout)      Cin=1152, 1x1 -> g_iral  (v+b)
//   MODE 3: g_h                        Cin=128, 3x3 -> g_off    (v+b)
// ---------------------------------------------------------------------------
template <int MODE>
DEV float fetch_in(const float* __restrict__ A, const float* __restrict__ Bp,
                   int b, int ci, int gy, int gx) {
    if (MODE == 0) {
        return (ci < CH) ? A[((b * CH + ci) * H + gy) * W + gx]
                         : Bp[((b * CH + (ci - CH)) * H + gy) * W + gx];
    } else if (MODE == 1) {
        float gv = g_gate[(b * H + gy) * W + gx];
        return (ci < CH) ? gv * g_iral[((b * CH + ci) * H + gy) * W + gx]
                         : (1.0f - gv) * A[((b * CH + (ci - CH)) * H + gy) * W + gx];
    } else if (MODE == 2) {
        return g_vals[((b * (CH * 9) + ci) * H + gy) * W + gx];
    } else {
        return g_h[((b * CH + ci) * H + gy) * W + gx];
    }
}

// ---------------------------------------------------------------------------
// Tiled implicit-GEMM conv.
// Block: 256 threads = 16 cout-groups x 16 px-groups. One (b, y) row (80 px),
// CO_TILE output channels. Register tile RCO x 5 per thread.
// ---------------------------------------------------------------------------
template <int MODE>
__global__ __launch_bounds__(256)
void conv_kernel(const float* __restrict__ A, const float* __restrict__ Bp,
                 const float* __restrict__ wgt,
                 const float* __restrict__ bias_or_bn,
                 const float* __restrict__ res_scale,
                 float* __restrict__ out_param) {
    constexpr int KS   = (MODE == 2) ? 1 : 3;
    constexpr int KS2  = KS * KS;
    constexpr int CIN  = (MODE == 2) ? (CH * 9) : ((MODE == 3) ? CH : 2 * CH);
    constexpr int COUT = (MODE == 3) ? 27 : CH;
    constexpr int RCO  = (MODE == 3) ? 2 : 4;
    constexpr int CO_TILE = 16 * RCO;
    constexpr int CO_PAD  = CO_TILE + 4;     // keeps float4/float2 alignment, breaks bank stride
    constexpr int CC   = 16;                 // input-channel chunk
    constexpr int S    = CC * KS2;
    constexpr int XW   = (KS == 3) ? (W + 2) : W;

    extern __shared__ float sm[];
    float* sW = sm;                          // [S][CO_PAD]
    float* sI = sm + S * CO_PAD;             // [CC][KS][XW]

    const int tid = threadIdx.x;
    const int tco = tid & 15;
    const int tpx = tid >> 4;
    const int x0  = tpx * 5;
    const int b   = blockIdx.x / H;
    const int y   = blockIdx.x % H;
    const int co_base = blockIdx.y * CO_TILE;

    float acc[RCO][5];
#pragma unroll
    for (int r = 0; r < RCO; r++)
#pragma unroll
        for (int p = 0; p < 5; p++) acc[r][p] = 0.0f;

    for (int ci0 = 0; ci0 < CIN; ci0 += CC) {
        __syncthreads();
        // ---- stage weights: sW[s][co] = w[co_base+co][ci0..ci0+CC)[kk]
        for (int idx = tid; idx < CO_TILE * S; idx += 256) {
            int co = idx / S;
            int s  = idx % S;
            int cog = co_base + co;
            float v = 0.0f;
            if (cog < COUT) v = wgt[cog * (CIN * KS2) + ci0 * KS2 + s];
            sW[s * CO_PAD + co] = v;
        }
        // ---- stage inputs (halo row for 3x3)
        for (int idx = tid; idx < CC * KS * XW; idx += 256) {
            int ci  = idx / (KS * XW);
            int rem = idx % (KS * XW);
            int ry  = rem / XW;
            int xx  = rem % XW;
            float v = 0.0f;
            if (KS == 3) {
                int gy = y + ry - 1;
                int gx = xx - 1;
                if (gy >= 0 && gy < H && gx >= 0 && gx < W)
                    v = fetch_in<MODE>(A, Bp, b, ci0 + ci, gy, gx);
            } else {
                v = fetch_in<MODE>(A, Bp, b, ci0 + ci, y, xx);
            }
            sI[(ci * KS + ry) * XW + xx] = v;
        }
        __syncthreads();
        // ---- FMA main loop
        for (int ci = 0; ci < CC; ++ci) {
#pragma unroll
            for (int kk = 0; kk < KS2; ++kk) {
                const int s = ci * KS2 + kk;
                const float* wp = &sW[s * CO_PAD + tco * RCO];
                float wv[RCO];
                if (RCO == 4) {
                    float4 w4 = *reinterpret_cast<const float4*>(wp);
                    wv[0] = w4.x; wv[1] = w4.y; wv[2] = w4.z; wv[3] = w4.w;
                } else {
                    float2 w2 = *reinterpret_cast<const float2*>(wp);
                    wv[0] = w2.x; wv[1] = w2.y;
                }
                const int ky = kk / KS;
                const int kx = kk - ky * KS;
                const float* ip = &sI[(ci * KS + ky) * XW + x0 + kx];
#pragma unroll
                for (int p = 0; p < 5; p++) {
                    float v = ip[p];
#pragma unroll
                    for (int r = 0; r < RCO; r++) acc[r][p] += wv[r] * v;
                }
            }
        }
    }

    // ---- epilogue
    float* optr = (MODE == 0) ? g_h
                : (MODE == 3) ? g_off
                : (MODE == 2) ? g_iral
                : out_param;
#pragma unroll
    for (int r = 0; r < RCO; r++) {
        int co = co_base + tco * RCO + r;
        if (co >= COUT) continue;
        float bnb, bns = 1.0f, rs = 0.0f;
        if (MODE == 1) {
            float gm = bias_or_bn[co];
            float bt = bias_or_bn[COUT + co];
            float mn = bias_or_bn[2 * COUT + co];
            float vr = bias_or_bn[3 * COUT + co];
            bns = gm * rsqrtf(vr + EPS);
            bnb = bt - mn * bns;
            rs  = *res_scale;
        } else {
            bnb = bias_or_bn[co];
        }
#pragma unroll
        for (int p = 0; p < 5; p++) {
            int x = x0 + p;
            int oidx = ((b * COUT + co) * H + y) * W + x;
            float v = acc[r][p];
            float o;
            if (MODE == 0)      o = silu_(v + bnb);
            else if (MODE == 1) o = silu_(v * bns + bnb) + rs * g_iral[oidx];
            else                o = v + bnb;
            optr[oidx] = o;
        }
    }
}

// ---------------------------------------------------------------------------
// Deformable bilinear sampling -> g_vals[b][c*9+k][y][x]
// offset conv channels: off_y(k)=ch 2k, off_x(k)=ch 2k+1, mask(k)=sigmoid(ch 18+k)
// ---------------------------------------------------------------------------
__global__ __launch_bounds__(256)
void deform_kernel(const float* __restrict__ ir) {
    const int blk   = blockIdx.x;
    const int ytile = blk % 27;
    const int bk    = blk / 27;
    const int k     = bk % 9;
    const int b     = bk / 9;
    const int tid   = threadIdx.x;
    if (tid >= 240) return;
    const int y = ytile * 3 + tid / 80;
    const int x = tid % 80;
    if (y >= H) return;

    const float* obase = g_off + (b * 27) * HW + y * W + x;
    float oy = obase[(2 * k) * HW];
    float ox = obase[(2 * k + 1) * HW];
    float m  = sigm_(obase[(18 + k) * HW]);

    const int ky = k / 3 - 1;
    const int kx = k % 3 - 1;
    float ys = oy + (float)(ky + y);
    float xs = ox + (float)(kx + x);
    float fy = floorf(ys), fx = floorf(xs);
    float wy = ys - fy,    wx = xs - fx;
    int y0 = (int)fy, x0 = (int)fx;
    int y1 = y0 + 1,  x1 = x0 + 1;
    bool vy0 = (y0 >= 0) && (y0 < H);
    bool vy1 = (y1 >= 0) && (y1 < H);
    bool vx0 = (x0 >= 0) && (x0 < W);
    bool vx1 = (x1 >= 0) && (x1 < W);
    float w00 = (1.0f - wy) * (1.0f - wx) * m * ((vy0 && vx0) ? 1.0f : 0.0f);
    float w01 = (1.0f - wy) * wx          * m * ((vy0 && vx1) ? 1.0f : 0.0f);
    float w10 = wy          * (1.0f - wx) * m * ((vy1 && vx0) ? 1.0f : 0.0f);
    float w11 = wy          * wx          * m * ((vy1 && vx1) ? 1.0f : 0.0f);
    int cy0 = min(max(y0, 0), H - 1), cy1 = min(max(y1, 0), H - 1);
    int cx0 = min(max(x0, 0), W - 1), cx1 = min(max(x1, 0), W - 1);
    int i00 = cy0 * W + cx0, i01 = cy0 * W + cx1;
    int i10 = cy1 * W + cx0, i11 = cy1 * W + cx1;

    const float* ib = ir + b * CH * HW;
    float* vout = g_vals + (b * CH * 9 + k) * HW + y * W + x;
#pragma unroll 4
    for (int c = 0; c < CH; c++) {
        const float* p = ib + c * HW;
        float v = w00 * __ldg(p + i00) + w01 * __ldg(p + i01)
                + w10 * __ldg(p + i10) + w11 * __ldg(p + i11);
        vout[c * 9 * HW] = v;
    }
}

// ---------------------------------------------------------------------------
// Gate stage 1: 1x1 conv 256 -> 16 + BN + SiLU -> g_g1
// ---------------------------------------------------------------------------
__global__ __launch_bounds__(256)
void gate1_kernel(const float* __restrict__ rgb,
                  const float* __restrict__ wg1,
                  const float* __restrict__ bng1) {
    __shared__ float sg[2 * CH * MID];   // [ci][o]
    const int tid = threadIdx.x;
    for (int i = tid; i < 2 * CH * MID; i += 256) {
        int ci = i >> 4, o = i & 15;
        sg[i] = wg1[o * (2 * CH) + ci];
    }
    __syncthreads();
    const int idx = blockIdx.x * 256 + tid;
    if (idx >= Bn * HW) return;
    const int b = idx / HW, p = idx % HW;

    float acc[MID];
#pragma unroll
    for (int o = 0; o < MID; o++) acc[o] = 0.0f;

    const float* rp = rgb    + b * CH * HW + p;
    const float* ip = g_iral + b * CH * HW + p;
    for (int ci = 0; ci < CH; ci++) {
        float v = rp[ci * HW];
        const float* w = &sg[ci * MID];
#pragma unroll
        for (int o = 0; o < MID; o++) acc[o] += w[o] * v;
    }
    for (int ci = 0; ci < CH; ci++) {
        float v = ip[ci * HW];
        const float* w = &sg[(CH + ci) * MID];
#pragma unroll
        for (int o = 0; o < MID; o++) acc[o] += w[o] * v;
    }
#pragma unroll
    for (int o = 0; o < MID; o++) {
        float gm = bng1[o], bt = bng1[MID + o];
        float mn = bng1[2 * MID + o], vr = bng1[3 * MID + o];
        float sc = gm * rsqrtf(vr + EPS);
        g_g1[(b * MID + o) * HW + p] = silu_(acc[o] * sc + bt - mn * sc);
    }
}

// ---------------------------------------------------------------------------
// Gate stages 2+3: depthwise 3x3 + BN + SiLU, then 1x1 16->1 + sigmoid -> g_gate
// ---------------------------------------------------------------------------
__global__ __launch_bounds__(256)
void gate23_kernel(const float* __restrict__ wg2,
                   const float* __restrict__ bng2,
                   const float* __restrict__ wg3,
                   const float* __restrict__ bg3) {
    const int idx = blockIdx.x * 256 + threadIdx.x;
    if (idx >= Bn * HW) return;
    const int b = idx / HW, p = idx % HW;
    const int y = p / W, x = p % W;

    float s3 = __ldg(bg3);
#pragma unroll
    for (int o = 0; o < MID; o++) {
        const float* gp = g_g1 + (b * MID + o) * HW;
        float s = 0.0f;
#pragma unroll
        for (int ky = 0; ky < 3; ky++) {
            int yy = y + ky - 1;
            if (yy < 0 || yy >= H) continue;
#pragma unroll
            for (int kx = 0; kx < 3; kx++) {
                int xx = x + kx - 1;
                if (xx < 0 || xx >= W) continue;
                s += gp[yy * W + xx] * __ldg(&wg2[o * 9 + ky * 3 + kx]);
            }
        }
        float gm = __ldg(&bng2[o]), bt = __ldg(&bng2[MID + o]);
        float mn = __ldg(&bng2[2 * MID + o]), vr = __ldg(&bng2[3 * MID + o]);
        float sc = gm * rsqrtf(vr + EPS);
        s3 += silu_(s * sc + bt - mn * sc) * __ldg(&wg3[o]);
    }
    g_gate[b * HW + p] = sigm_(s3);
}

// ---------------------------------------------------------------------------
// Launcher
// ---------------------------------------------------------------------------
extern "C" void kernel_launch(void* const* d_in, const int* in_sizes, int n_in,
                              void* d_out, int out_size) {
    const float* rgb    = (const float*)d_in[0];
    const float* ir     = (const float*)d_in[1];
    const float* w_off1 = (const float*)d_in[2];
    const float* b_off1 = (const float*)d_in[3];
    const float* w_off2 = (const float*)d_in[4];
    const float* b_off2 = (const float*)d_in[5];
    const float* w_dcn  = (const float*)d_in[6];
    const float* b_dcn  = (const float*)d_in[7];
    const float* w_g1   = (const float*)d_in[8];
    const float* bn_g1  = (const float*)d_in[9];
    const float* w_g2   = (const float*)d_in[10];
    const float* bn_g2  = (const float*)d_in[11];
    const float* w_g3   = (const float*)d_in[12];
    const float* b_g3   = (const float*)d_in[13];
    const float* w_f    = (const float*)d_in[14];
    const float* bn_f   = (const float*)d_in[15];
    const float* rscale = (const float*)d_in[16];
    float* out = (float*)d_out;

    const int sm_big = (144 * 68 + 16 * 3 * 82) * 4;   // 54912 B (modes 0,1)
    const int sm_off = (144 * 36 + 16 * 3 * 82) * 4;   // 36480 B (mode 3)
    const int sm_dcn = (16 * 68 + 16 * 80) * 4;        //  9472 B (mode 2)

    cudaFuncSetAttribute(conv_kernel<0>, cudaFuncAttributeMaxDynamicSharedMemorySize, sm_big);
    cudaFuncSetAttribute(conv_kernel<1>, cudaFuncAttributeMaxDynamicSharedMemorySize, sm_big);

    // 1) h = silu(conv3x3(concat(rgb, ir), w_off1) + b_off1)
    conv_kernel<0><<<dim3(Bn * H, 2), 256, sm_big>>>(rgb, ir, w_off1, b_off1, nullptr, nullptr);
    // 2) raw offset/mask conv (27 ch)
    conv_kernel<3><<<dim3(Bn * H, 1), 256, sm_off>>>(nullptr, nullptr, w_off2, b_off2, nullptr, nullptr);
    // 3) deformable bilinear sampling * mask -> g_vals
    deform_kernel<<<Bn * 9 * 27, 256>>>(ir);
    // 4) ir_aligned = vals . w_dcn + b_dcn   (1x1 conv, Cin=1152)
    conv_kernel<2><<<dim3(Bn * H, 2), 256, sm_dcn>>>(nullptr, nullptr, w_dcn, b_dcn, nullptr, nullptr);
    // 5) gate stage 1
    gate1_kernel<<<(Bn * HW + 255) / 256, 256>>>(rgb, w_g1, bn_g1);
    // 6) gate stages 2+3
    gate23_kernel<<<(Bn * HW + 255) / 256, 256>>>(w_g2, bn_g2, w_g3, b_g3);
    // 7) fused conv + BN + SiLU + residual -> out
    conv_kernel<1><<<dim3(Bn * H, 2), 256, sm_big>>>(rgb, nullptr, w_f, bn_f, rscale, out);
}

// round 2
// speedup vs baseline: 1.2137x; 1.2137x over previous
#include <cuda_runtime.h>

// ---------------------------------------------------------------------------
// Problem constants
// ---------------------------------------------------------------------------
constexpr int Bn  = 8;
constexpr int CH  = 128;
constexpr int H   = 80;
constexpr int W   = 80;
constexpr int HW  = H * W;
constexpr int MID = 16;
constexpr float EPS = 1e-5f;

// ---------------------------------------------------------------------------
// Scratch (static __device__ globals — allocation-free per harness rules)
// ---------------------------------------------------------------------------
__device__ float g_h[Bn * CH * HW];            // silu(conv_off1)
__device__ float g_off[Bn * 27 * HW];          // raw offset/mask conv
__device__ float g_vals[Bn * CH * 9 * HW];     // deform samples
__device__ float g_iral[Bn * CH * HW];         // ir_aligned
__device__ float g_g1[Bn * MID * HW];          // gate stage-1
__device__ float g_gate[Bn * HW];              // final gate

#define DEV __device__ __forceinline__
typedef unsigned long long ull;

DEV float sigm_(float x) { return 1.0f / (1.0f + __expf(-x)); }
DEV float silu_(float x) { return x * sigm_(x); }

// packed f32x2 helpers (FFMA2 is only reachable via PTX fma.rn.f32x2)
DEV void ffma2(ull& d, ull a, ull b) {
    asm("fma.rn.f32x2 %0, %1, %2, %0;" : "+l"(d) : "l"(a), "l"(b));
}
DEV ull dup2(float w) {
    ull u; asm("mov.b64 %0, {%1, %1};" : "=l"(u) : "f"(w)); return u;
}
DEV void unpack2(ull u, float& x, float& y) {
    asm("mov.b64 {%0, %1}, %2;" : "=f"(x), "=f"(y) : "l"(u));
}

// ---------------------------------------------------------------------------
// Input fetch per conv mode
//   MODE 0: concat(rgb, ir)            Cin=256, 3x3 -> g_h      (silu(v+b))
//   MODE 1: concat(g*iral, (1-g)*rgb)  Cin=256, 3x3 -> out      (silu(bn)+res)
//   MODE 2: g_vals (c*9+k layout)      Cin=1152, 1x1 -> g_iral  (v+b)
//   MODE 3: g_h                        Cin=128, 3x3 -> g_off    (v+b)
// ---------------------------------------------------------------------------
template <int MODE>
DEV float fetch_in(const float* __restrict__ A, const float* __restrict__ Bp,
                   int b, int ci, int gy, int gx) {
    if (MODE == 0) {
        return (ci < CH) ? A[((b * CH + ci) * H + gy) * W + gx]
                         : Bp[((b * CH + (ci - CH)) * H + gy) * W + gx];
    } else if (MODE == 1) {
        float gv = g_gate[(b * H + gy) * W + gx];
        return (ci < CH) ? gv * g_iral[((b * CH + ci) * H + gy) * W + gx]
                         : (1.0f - gv) * A[((b * CH + (ci - CH)) * H + gy) * W + gx];
    } else if (MODE == 2) {
        return g_vals[((b * (CH * 9) + ci) * H + gy) * W + gx];
    } else {
        return g_h[((b * CH + ci) * H + gy) * W + gx];
    }
}

// ---------------------------------------------------------------------------
// Tiled implicit-GEMM conv, 2 output rows per block, packed f32x2 math.
// Block: 256 threads = 16 cout-groups x 16 px-groups (5 px each).
// Each thread: RCO couts x 5 px x 2 rows, accumulated in f32x2 registers.
// SMEM input tile is row-interleaved float2: sI[ci][ry][x] =
//   ( in[y0-1+ry][x], in[y0+ry][x] )  so one LDS.64 feeds both output rows.
// ---------------------------------------------------------------------------
template <int MODE>
__global__ __launch_bounds__(256)
void conv_kernel(const float* __restrict__ A, const float* __restrict__ Bp,
                 const float* __restrict__ wgt,
                 const float* __restrict__ bias_or_bn,
                 const float* __restrict__ res_scale,
                 float* __restrict__ out_param) {
    constexpr int KS   = (MODE == 2) ? 1 : 3;
    constexpr int KS2  = KS * KS;
    constexpr int CIN  = (MODE == 2) ? (CH * 9) : ((MODE == 3) ? CH : 2 * CH);
    constexpr int COUT = (MODE == 3) ? 27 : CH;
    constexpr int RCO  = (MODE == 3) ? 2 : 4;
    constexpr int CO_TILE = 16 * RCO;
    constexpr int CO_PAD  = CO_TILE + 4;
    constexpr int CC   = (MODE == 2) ? 32 : 16;    // input-channel chunk
    constexpr int S    = CC * KS2;
    constexpr int XW   = (KS == 3) ? (W + 2) : W;

    extern __shared__ float sm[];
    float*  sW = sm;                                  // [S][CO_PAD]
    float2* sI = (float2*)(sm + S * CO_PAD);          // [CC][KS][XW]

    const int tid = threadIdx.x;
    const int tco = tid & 15;
    const int tpx = tid >> 4;
    const int x0  = tpx * 5;
    const int b   = blockIdx.x / (H / 2);
    const int y0  = (blockIdx.x % (H / 2)) * 2;
    const int co_base = blockIdx.y * CO_TILE;

    ull acc[RCO][5];
#pragma unroll
    for (int r = 0; r < RCO; r++)
#pragma unroll
        for (int p = 0; p < 5; p++) acc[r][p] = 0ull;

    for (int ci0 = 0; ci0 < CIN; ci0 += CC) {
        __syncthreads();
        // ---- stage weights: sW[s][co]
        for (int idx = tid; idx < CO_TILE * S; idx += 256) {
            int co = idx / S;
            int s  = idx % S;
            int cog = co_base + co;
            float v = 0.0f;
            if (cog < COUT) v = wgt[cog * (CIN * KS2) + ci0 * KS2 + s];
            sW[s * CO_PAD + co] = v;
        }
        // ---- stage inputs, row pair interleaved
        for (int idx = tid; idx < CC * KS * XW; idx += 256) {
            int ci  = idx / (KS * XW);
            int rem = idx % (KS * XW);
            int ry  = rem / XW;
            int xx  = rem % XW;
            float v0 = 0.0f, v1 = 0.0f;
            if (KS == 3) {
                int gx  = xx - 1;
                int gy0 = y0 - 1 + ry;        // row for output y0
                int gy1 = gy0 + 1;            // row for output y0+1 (>=0 always)
                if (gx >= 0 && gx < W) {
                    if (gy0 >= 0 && gy0 < H) v0 = fetch_in<MODE>(A, Bp, b, ci0 + ci, gy0, gx);
                    if (gy1 < H)             v1 = fetch_in<MODE>(A, Bp, b, ci0 + ci, gy1, gx);
                }
            } else {
                v0 = fetch_in<MODE>(A, Bp, b, ci0 + ci, y0, xx);
                v1 = fetch_in<MODE>(A, Bp, b, ci0 + ci, y0 + 1, xx);
            }
            sI[(ci * KS + ry) * XW + xx] = make_float2(v0, v1);
        }
        __syncthreads();
        // ---- packed FMA main loop
        for (int ci = 0; ci < CC; ++ci) {
#pragma unroll
            for (int kk = 0; kk < KS2; ++kk) {
                const int s = ci * KS2 + kk;
                const float* wp = &sW[s * CO_PAD + tco * RCO];
                ull w2[RCO];
                if (RCO == 4) {
                    float4 w4 = *reinterpret_cast<const float4*>(wp);
                    w2[0] = dup2(w4.x); w2[1] = dup2(w4.y);
                    w2[2] = dup2(w4.z); w2[3] = dup2(w4.w);
                } else {
                    float2 wv = *reinterpret_cast<const float2*>(wp);
                    w2[0] = dup2(wv.x); w2[1] = dup2(wv.y);
                }
                const int ky = kk / KS;
                const int kx = kk - ky * KS;
                const ull* ip = reinterpret_cast<const ull*>(
                    &sI[(ci * KS + ky) * XW + x0 + kx]);
                ull vv[5];
#pragma unroll
                for (int p = 0; p < 5; p++) vv[p] = ip[p];
#pragma unroll
                for (int p = 0; p < 5; p++)
#pragma unroll
                    for (int r = 0; r < RCO; r++) ffma2(acc[r][p], w2[r], vv[p]);
            }
        }
    }

    // ---- epilogue (two rows)
    float* optr = (MODE == 0) ? g_h
                : (MODE == 3) ? g_off
                : (MODE == 2) ? g_iral
                : out_param;
#pragma unroll
    for (int r = 0; r < RCO; r++) {
        int co = co_base + tco * RCO + r;
        if (co >= COUT) continue;
        float bnb, bns = 1.0f, rs = 0.0f;
        if (MODE == 1) {
            float gm = bias_or_bn[co];
            float bt = bias_or_bn[COUT + co];
            float mn = bias_or_bn[2 * COUT + co];
            float vr = bias_or_bn[3 * COUT + co];
            bns = gm * rsqrtf(vr + EPS);
            bnb = bt - mn * bns;
            rs  = *res_scale;
        } else {
            bnb = bias_or_bn[co];
        }
#pragma unroll
        for (int p = 0; p < 5; p++) {
            int x = x0 + p;
            int o0 = ((b * COUT + co) * H + y0) * W + x;
            int o1 = o0 + W;
            float a0, a1;
            unpack2(acc[r][p], a0, a1);
            if (MODE == 0) {
                optr[o0] = silu_(a0 + bnb);
                optr[o1] = silu_(a1 + bnb);
            } else if (MODE == 1) {
                optr[o0] = silu_(a0 * bns + bnb) + rs * g_iral[o0];
                optr[o1] = silu_(a1 * bns + bnb) + rs * g_iral[o1];
            } else {
                optr[o0] = a0 + bnb;
                optr[o1] = a1 + bnb;
            }
        }
    }
}

// ---------------------------------------------------------------------------
// Deformable bilinear sampling -> g_vals[b][c*9+k][y][x]
// ---------------------------------------------------------------------------
__global__ __launch_bounds__(256)
void deform_kernel(const float* __restrict__ ir) {
    const int blk   = blockIdx.x;
    const int ytile = blk % 27;
    const int bk    = blk / 27;
    const int k     = bk % 9;
    const int b     = bk / 9;
    const int tid   = threadIdx.x;
    if (tid >= 240) return;
    const int y = ytile * 3 + tid / 80;
    const int x = tid % 80;
    if (y >= H) return;

    const float* obase = g_off + (b * 27) * HW + y * W + x;
    float oy = obase[(2 * k) * HW];
    float ox = obase[(2 * k + 1) * HW];
    float m  = sigm_(obase[(18 + k) * HW]);

    const int ky = k / 3 - 1;
    const int kx = k % 3 - 1;
    float ys = oy + (float)(ky + y);
    float xs = ox + (float)(kx + x);
    float fy = floorf(ys), fx = floorf(xs);
    float wy = ys - fy,    wx = xs - fx;
    int y0 = (int)fy, x0 = (int)fx;
    int y1 = y0 + 1,  x1 = x0 + 1;
    bool vy0 = (y0 >= 0) && (y0 < H);
    bool vy1 = (y1 >= 0) && (y1 < H);
    bool vx0 = (x0 >= 0) && (x0 < W);
    bool vx1 = (x1 >= 0) && (x1 < W);
    float w00 = (1.0f - wy) * (1.0f - wx) * m * ((vy0 && vx0) ? 1.0f : 0.0f);
    float w01 = (1.0f - wy) * wx          * m * ((vy0 && vx1) ? 1.0f : 0.0f);
    float w10 = wy          * (1.0f - wx) * m * ((vy1 && vx0) ? 1.0f : 0.0f);
    float w11 = wy          * wx          * m * ((vy1 && vx1) ? 1.0f : 0.0f);
    int cy0 = min(max(y0, 0), H - 1), cy1 = min(max(y1, 0), H - 1);
    int cx0 = min(max(x0, 0), W - 1), cx1 = min(max(x1, 0), W - 1);
    int i00 = cy0 * W + cx0, i01 = cy0 * W + cx1;
    int i10 = cy1 * W + cx0, i11 = cy1 * W + cx1;

    const float* ib = ir + b * CH * HW;
    float* vout = g_vals + (b * CH * 9 + k) * HW + y * W + x;
#pragma unroll 4
    for (int c = 0; c < CH; c++) {
        const float* p = ib + c * HW;
        float v = w00 * __ldg(p + i00) + w01 * __ldg(p + i01)
                + w10 * __ldg(p + i10) + w11 * __ldg(p + i11);
        vout[c * 9 * HW] = v;
    }
}

// ---------------------------------------------------------------------------
// Gate stage 1: 1x1 conv 256 -> 16 + BN + SiLU -> g_g1
// ---------------------------------------------------------------------------
__global__ __launch_bounds__(256)
void gate1_kernel(const float* __restrict__ rgb,
                  const float* __restrict__ wg1,
                  const float* __restrict__ bng1) {
    __shared__ float sg[2 * CH * MID];   // [ci][o]
    const int tid = threadIdx.x;
    for (int i = tid; i < 2 * CH * MID; i += 256) {
        int ci = i >> 4, o = i & 15;
        sg[i] = wg1[o * (2 * CH) + ci];
    }
    __syncthreads();
    const int idx = blockIdx.x * 256 + tid;
    if (idx >= Bn * HW) return;
    const int b = idx / HW, p = idx % HW;

    float acc[MID];
#pragma unroll
    for (int o = 0; o < MID; o++) acc[o] = 0.0f;

    const float* rp = rgb    + b * CH * HW + p;
    const float* ip = g_iral + b * CH * HW + p;
    for (int ci = 0; ci < CH; ci++) {
        float v = rp[ci * HW];
        const float* w = &sg[ci * MID];
#pragma unroll
        for (int o = 0; o < MID; o++) acc[o] += w[o] * v;
    }
    for (int ci = 0; ci < CH; ci++) {
        float v = ip[ci * HW];
        const float* w = &sg[(CH + ci) * MID];
#pragma unroll
        for (int o = 0; o < MID; o++) acc[o] += w[o] * v;
    }
#pragma unroll
    for (int o = 0; o < MID; o++) {
        float gm = bng1[o], bt = bng1[MID + o];
        float mn = bng1[2 * MID + o], vr = bng1[3 * MID + o];
        float sc = gm * rsqrtf(vr + EPS);
        g_g1[(b * MID + o) * HW + p] = silu_(acc[o] * sc + bt - mn * sc);
    }
}

// ---------------------------------------------------------------------------
// Gate stages 2+3: depthwise 3x3 + BN + SiLU, then 1x1 16->1 + sigmoid
// ---------------------------------------------------------------------------
__global__ __launch_bounds__(256)
void gate23_kernel(const float* __restrict__ wg2,
                   const float* __restrict__ bng2,
                   const float* __restrict__ wg3,
                   const float* __restrict__ bg3) {
    const int idx = blockIdx.x * 256 + threadIdx.x;
    if (idx >= Bn * HW) return;
    const int b = idx / HW, p = idx % HW;
    const int y = p / W, x = p % W;

    float s3 = __ldg(bg3);
#pragma unroll
    for (int o = 0; o < MID; o++) {
        const float* gp = g_g1 + (b * MID + o) * HW;
        float s = 0.0f;
#pragma unroll
        for (int ky = 0; ky < 3; ky++) {
            int yy = y + ky - 1;
            if (yy < 0 || yy >= H) continue;
#pragma unroll
            for (int kx = 0; kx < 3; kx++) {
                int xx = x + kx - 1;
                if (xx < 0 || xx >= W) continue;
                s += gp[yy * W + xx] * __ldg(&wg2[o * 9 + ky * 3 + kx]);
            }
        }
        float gm = __ldg(&bng2[o]), bt = __ldg(&bng2[MID + o]);
        float mn = __ldg(&bng2[2 * MID + o]), vr = __ldg(&bng2[3 * MID + o]);
        float sc = gm * rsqrtf(vr + EPS);
        s3 += silu_(s * sc + bt - mn * sc) * __ldg(&wg3[o]);
    }
    g_gate[b * HW + p] = sigm_(s3);
}

// ---------------------------------------------------------------------------
// Launcher
// ---------------------------------------------------------------------------
extern "C" void kernel_launch(void* const* d_in, const int* in_sizes, int n_in,
                              void* d_out, int out_size) {
    const float* rgb    = (const float*)d_in[0];
    const float* ir     = (const float*)d_in[1];
    const float* w_off1 = (const float*)d_in[2];
    const float* b_off1 = (const float*)d_in[3];
    const float* w_off2 = (const float*)d_in[4];
    const float* b_off2 = (const float*)d_in[5];
    const float* w_dcn  = (const float*)d_in[6];
    const float* b_dcn  = (const float*)d_in[7];
    const float* w_g1   = (const float*)d_in[8];
    const float* bn_g1  = (const float*)d_in[9];
    const float* w_g2   = (const float*)d_in[10];
    const float* bn_g2  = (const float*)d_in[11];
    const float* w_g3   = (const float*)d_in[12];
    const float* b_g3   = (const float*)d_in[13];
    const float* w_f    = (const float*)d_in[14];
    const float* bn_f   = (const float*)d_in[15];
    const float* rscale = (const float*)d_in[16];
    float* out = (float*)d_out;

    // shared sizes: weights [S][CO_PAD] floats + inputs [CC][KS][XW] float2
    const int sm_big = (144 * 68) * 4 + (16 * 3 * 82) * 8;   // 70656 B (modes 0,1)
    const int sm_off = (144 * 36) * 4 + (16 * 3 * 82) * 8;   // 52224 B (mode 3)
    const int sm_dcn = (32 * 68) * 4 + (32 * 80) * 8;        // 29184 B (mode 2)

    cudaFuncSetAttribute(conv_kernel<0>, cudaFuncAttributeMaxDynamicSharedMemorySize, sm_big);
    cudaFuncSetAttribute(conv_kernel<1>, cudaFuncAttributeMaxDynamicSharedMemorySize, sm_big);
    cudaFuncSetAttribute(conv_kernel<3>, cudaFuncAttributeMaxDynamicSharedMemorySize, sm_off);

    const int BX = Bn * (H / 2);   // 320 row-pair blocks

    // 1) h = silu(conv3x3(concat(rgb, ir), w_off1) + b_off1)
    conv_kernel<0><<<dim3(BX, 2), 256, sm_big>>>(rgb, ir, w_off1, b_off1, nullptr, nullptr);
    // 2) raw offset/mask conv (27 ch)
    conv_kernel<3><<<dim3(BX, 1), 256, sm_off>>>(nullptr, nullptr, w_off2, b_off2, nullptr, nullptr);
    // 3) deformable bilinear sampling * mask -> g_vals
    deform_kernel<<<Bn * 9 * 27, 256>>>(ir);
    // 4) ir_aligned = vals . w_dcn + b_dcn   (1x1 conv, Cin=1152)
    conv_kernel<2><<<dim3(BX, 2), 256, sm_dcn>>>(nullptr, nullptr, w_dcn, b_dcn, nullptr, nullptr);
    // 5) gate stage 1
    gate1_kernel<<<(Bn * HW + 255) / 256, 256>>>(rgb, w_g1, bn_g1);
    // 6) gate stages 2+3
    gate23_kernel<<<(Bn * HW + 255) / 256, 256>>>(w_g2, bn_g2, w_g3, b_g3);
    // 7) fused conv + BN + SiLU + residual -> out
    conv_kernel<1><<<dim3(BX, 2), 256, sm_big>>>(rgb, nullptr, w_f, bn_f, rscale, out);
}